// round 6
// baseline (speedup 1.0000x reference)
#include <cuda_runtime.h>
#include <cstdint>

#define N_DIM 1024
#define BM 64
#define BN 64
#define BK 32
#define NKT (N_DIM / BK)          // 32
#define NTH 128

#define ABYTES (BM * BK * 4)      // 8192
#define BBYTES (BN * BK * 4)      // 8192
#define STAGE  (ABYTES + BBYTES)  // 16384
#define SMEM_TOTAL (2 * STAGE)    // 32768

// scratch (allocation-free rules)
__device__ float g_t1c[N_DIM * N_DIM];   // tf32(t1)
__device__ float g_t2c[N_DIM * N_DIM];   // tf32(t2) = P_1
__device__ float g_sA [N_DIM * N_DIM];
__device__ float g_sB [N_DIM * N_DIM];
__device__ float g_pA [N_DIM * N_DIM];
__device__ float g_pB [N_DIM * N_DIM];
__device__ float g_U  [N_DIM * N_DIM];

__device__ __forceinline__ uint32_t smem_u32(const void* p) {
    uint32_t r;
    asm("{ .reg .u64 t; cvta.to.shared.u64 t, %1; cvt.u32.u64 %0, t; }" : "=r"(r) : "l"(p));
    return r;
}
__device__ __forceinline__ float to_tf32(float x) {
    uint32_t u;
    asm("cvt.rna.tf32.f32 %0, %1;" : "=r"(u) : "f"(x));
    return __uint_as_float(u);
}
__device__ __forceinline__ void cp16(uint32_t dst, const float* src) {
    asm volatile("cp.async.cg.shared.global [%0], [%1], 16;"
                 :: "r"(dst), "l"(src) : "memory");
}
__device__ __forceinline__ void ldm_x4(uint32_t* r, uint32_t addr) {
    asm volatile("ldmatrix.sync.aligned.m8n8.x4.shared.b16 {%0,%1,%2,%3}, [%4];"
                 : "=r"(r[0]), "=r"(r[1]), "=r"(r[2]), "=r"(r[3]) : "r"(addr));
}
__device__ __forceinline__ void mma_tf32(float* d, const uint32_t* a,
                                         uint32_t b0, uint32_t b1) {
    asm volatile(
        "mma.sync.aligned.m16n8k8.row.col.f32.tf32.tf32.f32 "
        "{%0,%1,%2,%3}, {%4,%5,%6,%7}, {%8,%9}, {%0,%1,%2,%3};"
        : "+f"(d[0]), "+f"(d[1]), "+f"(d[2]), "+f"(d[3])
        : "r"(a[0]), "r"(a[1]), "r"(a[2]), "r"(a[3]), "r"(b0), "r"(b1));
}

// A tile [BM x BK] via cp.async, K-major swizzled smem (row = m, 128B rows, 8 chunks)
__device__ __forceinline__ void issueA(const float* __restrict__ A,
                                       int bm, int kt, uint32_t base, int tid) {
#pragma unroll
    for (int i = 0; i < 4; i++) {        // 512 16B chunks / 128 threads
        int f = tid + i * NTH;
        int row = f >> 3, c = f & 7;
        uint32_t dst = base + row * 128 + ((c ^ (row & 7)) << 4);
        cp16(dst, A + (size_t)(bm + row) * N_DIM + kt * BK + c * 4);
    }
    asm volatile("cp.async.commit_group;" ::: "memory");
}

// B tile [BK x BN] (normal orientation) -> regs; chunk f: n = f&63, c = f>>6 (0..7)
__device__ __forceinline__ void ldgB(const float* __restrict__ B,
                                     int bn, int kt, float4* v, int tid) {
#pragma unroll
    for (int i = 0; i < 4; i++) {
        int f = tid + i * NTH;
        int n = f & 63, c = f >> 6;
        const float* p = B + (size_t)(kt * BK + 4 * c) * N_DIM + bn + n;
        v[i].x = p[0];
        v[i].y = p[N_DIM];
        v[i].z = p[2 * N_DIM];
        v[i].w = p[3 * N_DIM];
    }
}
__device__ __forceinline__ void stsB(uint32_t Bb, const float4* v, int tid) {
#pragma unroll
    for (int i = 0; i < 4; i++) {
        int f = tid + i * NTH;
        int n = f & 63, c = f >> 6;
        uint32_t dst = Bb + n * 128 + ((c ^ (n & 7)) << 4);
        asm volatile("st.shared.v4.b32 [%0], {%1, %2, %3, %4};"
                     :: "r"(dst),
                        "r"(__float_as_uint(v[i].x)), "r"(__float_as_uint(v[i].y)),
                        "r"(__float_as_uint(v[i].z)), "r"(__float_as_uint(v[i].w))
                     : "memory");
    }
}

// z=0: C = bs*Bias + Bias2 + A@B (round if rnd). z=1: C1 = A1@B1 (rounded).
__global__ void __launch_bounds__(NTH, 2)
gemm_nn(const float* __restrict__ A, const float* __restrict__ B,
        const float* __restrict__ Bias, float bs,
        const float* __restrict__ Bias2,
        float* __restrict__ C, int rnd,
        const float* __restrict__ A1, const float* __restrict__ B1,
        float* __restrict__ C1)
{
    if (blockIdx.z) {
        A = A1; B = B1; C = C1;
        Bias = nullptr; Bias2 = nullptr; rnd = 1;
    }
    extern __shared__ char smem[];
    const uint32_t sb = smem_u32(smem);
    const int tid = threadIdx.x, lid = tid & 31, wid = tid >> 5;
    const int wm = (wid & 1) * 32, wn = (wid >> 1) * 32;   // 2x2 warps, 32x32 tiles
    const int bm = blockIdx.y * BM, bn = blockIdx.x * BN;

    float d[2][4][4];
#pragma unroll
    for (int i = 0; i < 2; i++)
#pragma unroll
        for (int j = 0; j < 4; j++)
#pragma unroll
            for (int k = 0; k < 4; k++) d[i][j][k] = 0.0f;

    const int sub = lid >> 3;
    const int r8  = lid & 7;
    const int a_row = wm + (sub & 1) * 8 + r8;
    const int a_chs = (sub >> 1);
    const int b_row = wn + (sub >> 1) * 8 + r8;
    const int b_chs = (sub & 1);

    float4 bv[4];
    issueA(A, bm, 0, sb, tid);
    ldgB(B, bn, 0, bv, tid);

    for (int kt = 0; kt < NKT; kt++) {
        const uint32_t buf = sb + (kt & 1) * STAGE;
        stsB(buf + ABYTES, bv, tid);
        if (kt + 1 < NKT) {
            issueA(A, bm, kt + 1, sb + ((kt + 1) & 1) * STAGE, tid);
            ldgB(B, bn, kt + 1, bv, tid);
            asm volatile("cp.async.wait_group 1;" ::: "memory");
        } else {
            asm volatile("cp.async.wait_group 0;" ::: "memory");
        }
        __syncthreads();

        const uint32_t Ab = buf;
        const uint32_t Bb = buf + ABYTES;
#pragma unroll
        for (int ks = 0; ks < 4; ks++) {
            uint32_t a[2][4], b[2][4];
#pragma unroll
            for (int mf = 0; mf < 2; mf++) {
                int row = a_row + mf * 16;
                int ch = ks * 2 + a_chs;
                ldm_x4(a[mf], Ab + row * 128 + ((ch ^ (row & 7)) << 4));
            }
#pragma unroll
            for (int j = 0; j < 2; j++) {
                int row = b_row + j * 16;
                int ch = ks * 2 + b_chs;
                ldm_x4(b[j], Bb + row * 128 + ((ch ^ (row & 7)) << 4));
            }
#pragma unroll
            for (int mf = 0; mf < 2; mf++)
#pragma unroll
                for (int nf = 0; nf < 4; nf++)
                    mma_tf32(d[mf][nf], a[mf],
                             b[nf >> 1][(nf & 1) * 2], b[nf >> 1][(nf & 1) * 2 + 1]);
        }
        __syncthreads();
    }

    const int g = lid >> 2, t = lid & 3;
#pragma unroll
    for (int mf = 0; mf < 2; mf++) {
#pragma unroll
        for (int nf = 0; nf < 4; nf++) {
            int row0 = bm + wm + mf * 16 + g;
            int col = bn + wn + nf * 8 + 2 * t;
            size_t off = (size_t)row0 * N_DIM + col;
            float2 o0 = make_float2(d[mf][nf][0], d[mf][nf][1]);
            float2 o1 = make_float2(d[mf][nf][2], d[mf][nf][3]);
            if (Bias) {
                const float* bp0 = Bias + off;
                float2 t0 = *reinterpret_cast<const float2*>(bp0);
                float2 t1v = *reinterpret_cast<const float2*>(bp0 + 8 * N_DIM);
                o0.x = fmaf(bs, t0.x, o0.x);
                o0.y = fmaf(bs, t0.y, o0.y);
                o1.x = fmaf(bs, t1v.x, o1.x);
                o1.y = fmaf(bs, t1v.y, o1.y);
            }
            if (Bias2) {
                const float* b2 = Bias2 + off;
                float2 u0 = *reinterpret_cast<const float2*>(b2);
                float2 u1 = *reinterpret_cast<const float2*>(b2 + 8 * N_DIM);
                o0.x += u0.x; o0.y += u0.y;
                o1.x += u1.x; o1.y += u1.y;
            }
            if (rnd) {
                o0.x = to_tf32(o0.x); o0.y = to_tf32(o0.y);
                o1.x = to_tf32(o1.x); o1.y = to_tf32(o1.y);
            }
            float* cp0 = C + off;
            *reinterpret_cast<float2*>(cp0) = o0;
            *reinterpret_cast<float2*>(cp0 + 8 * N_DIM) = o1;
        }
    }
}

// grid (1024, 2): y=0 rounds t1 -> o1, y=1 rounds t2 -> o2
__global__ void __launch_bounds__(256)
cvt2_k(const float* __restrict__ i1, const float* __restrict__ i2,
       float* __restrict__ o1, float* __restrict__ o2) {
    const float* in = blockIdx.y ? i2 : i1;
    float* out = blockIdx.y ? o2 : o1;
    int i = (blockIdx.x * 256 + threadIdx.x) * 4;
    float4 v = *reinterpret_cast<const float4*>(in + i);
    v.x = to_tf32(v.x); v.y = to_tf32(v.y);
    v.z = to_tf32(v.z); v.w = to_tf32(v.w);
    *reinterpret_cast<float4*>(out + i) = v;
}

extern "C" void kernel_launch(void* const* d_in, const int* in_sizes, int n_in,
                              void* d_out, int out_size)
{
    const float* t1 = (const float*)d_in[0];
    const float* t2 = (const float*)d_in[1];
    float* out = (float*)d_out;

    float *t1c, *t2c, *sA, *sB, *pA, *pB, *U;
    cudaGetSymbolAddress((void**)&t1c, g_t1c);
    cudaGetSymbolAddress((void**)&t2c, g_t2c);
    cudaGetSymbolAddress((void**)&sA, g_sA);
    cudaGetSymbolAddress((void**)&sB, g_sB);
    cudaGetSymbolAddress((void**)&pA, g_pA);
    cudaGetSymbolAddress((void**)&pB, g_pB);
    cudaGetSymbolAddress((void**)&U, g_U);

    cudaFuncSetAttribute(gemm_nn, cudaFuncAttributeMaxDynamicSharedMemorySize, SMEM_TOTAL);

    cvt2_k<<<dim3(N_DIM * N_DIM / 1024, 2), 256>>>(t1, t2, t1c, t2c);

    dim3 g1(N_DIM / BN, N_DIM / BM, 1);   // (16,16) = 256 CTAs
    dim3 g2(N_DIM / BN, N_DIM / BM, 2);   // merged: 512 CTAs

    // Pair map: X' = C + T X T, T = t2, C = t1 + t1@t2.
    // out ≈ S_8 + t1 (series tail ~3e-5 rel).  Doubling: U=P@S; S'=S+U@P; P'=P@P.
    //
    // L1: S1 = t1 + t1c@t2c -> sA  ||  P2 = t2c@t2c -> pA
    gemm_nn<<<g2, NTH, SMEM_TOTAL>>>(t1c, t2c, t1, 1.0f, nullptr, sA, 1,
                                     t2c, t2c, pA);
    // L2: U = t2c@S1
    gemm_nn<<<g1, NTH, SMEM_TOTAL>>>(t2c, sA, nullptr, 0.0f, nullptr, U, 1,
                                     nullptr, nullptr, nullptr);
    // L3: S2 = S1 + U@t2c -> sB
    gemm_nn<<<g1, NTH, SMEM_TOTAL>>>(U, t2c, sA, 1.0f, nullptr, sB, 1,
                                     nullptr, nullptr, nullptr);
    // L4: U2 = P2@S2 -> U  ||  P4 = P2@P2 -> pB
    gemm_nn<<<g2, NTH, SMEM_TOTAL>>>(pA, sB, nullptr, 0.0f, nullptr, U, 1,
                                     pA, pA, pB);
    // L5: S4 = S2 + U2@P2 -> sA
    gemm_nn<<<g1, NTH, SMEM_TOTAL>>>(U, pA, sB, 1.0f, nullptr, sA, 1,
                                     nullptr, nullptr, nullptr);
    // L6: U3 = P4@S4 -> U
    gemm_nn<<<g1, NTH, SMEM_TOTAL>>>(pB, sA, nullptr, 0.0f, nullptr, U, 1,
                                     nullptr, nullptr, nullptr);
    // L7: out = S4 + U3@P4 + t1  (fp32, no rounding)
    gemm_nn<<<g1, NTH, SMEM_TOTAL>>>(U, pB, sA, 1.0f, t1, out, 0,
                                     nullptr, nullptr, nullptr);
}

// round 7
// speedup vs baseline: 1.0891x; 1.0891x over previous
#include <cuda_runtime.h>
#include <cstdint>

#define N_DIM 1024
#define BM 64
#define BN 64
#define BK 64
#define NKT (N_DIM / BK)          // 16
#define NTH 128

#define ABYTES (BM * BK * 4)      // 16384
#define BBYTES (BN * BK * 4)      // 16384
#define STAGE  (ABYTES + BBYTES)  // 32768
#define SMEM_TOTAL (2 * STAGE)    // 65536

// scratch (allocation-free rules)
__device__ float g_t1c[N_DIM * N_DIM];   // tf32(t1)
__device__ float g_t2c[N_DIM * N_DIM];   // tf32(t2) = P_1
__device__ float g_sA [N_DIM * N_DIM];
__device__ float g_sB [N_DIM * N_DIM];
__device__ float g_pA [N_DIM * N_DIM];
__device__ float g_pB [N_DIM * N_DIM];
__device__ float g_U  [N_DIM * N_DIM];

__device__ __forceinline__ uint32_t smem_u32(const void* p) {
    uint32_t r;
    asm("{ .reg .u64 t; cvta.to.shared.u64 t, %1; cvt.u32.u64 %0, t; }" : "=r"(r) : "l"(p));
    return r;
}
__device__ __forceinline__ float to_tf32(float x) {
    uint32_t u;
    asm("cvt.rna.tf32.f32 %0, %1;" : "=r"(u) : "f"(x));
    return __uint_as_float(u);
}
__device__ __forceinline__ void cp16(uint32_t dst, const float* src) {
    asm volatile("cp.async.cg.shared.global [%0], [%1], 16;"
                 :: "r"(dst), "l"(src) : "memory");
}
__device__ __forceinline__ void ldm_x4(uint32_t* r, uint32_t addr) {
    asm volatile("ldmatrix.sync.aligned.m8n8.x4.shared.b16 {%0,%1,%2,%3}, [%4];"
                 : "=r"(r[0]), "=r"(r[1]), "=r"(r[2]), "=r"(r[3]) : "r"(addr));
}
__device__ __forceinline__ void mma_tf32(float* d, const uint32_t* a,
                                         uint32_t b0, uint32_t b1) {
    asm volatile(
        "mma.sync.aligned.m16n8k8.row.col.f32.tf32.tf32.f32 "
        "{%0,%1,%2,%3}, {%4,%5,%6,%7}, {%8,%9}, {%0,%1,%2,%3};"
        : "+f"(d[0]), "+f"(d[1]), "+f"(d[2]), "+f"(d[3])
        : "r"(a[0]), "r"(a[1]), "r"(a[2]), "r"(a[3]), "r"(b0), "r"(b1));
}

// A tile [BM x BK] via cp.async, K-major swizzled smem (row = m, 256B rows, 16 chunks)
__device__ __forceinline__ void issueA(const float* __restrict__ A,
                                       int bm, int kt, uint32_t base, int tid) {
#pragma unroll
    for (int i = 0; i < 8; i++) {        // 1024 16B chunks / 128 threads
        int f = tid + i * NTH;
        int row = f >> 4, c = f & 15;
        uint32_t dst = base + row * 256 + ((c ^ (row & 7)) << 4);
        cp16(dst, A + (size_t)(bm + row) * N_DIM + kt * BK + c * 4);
    }
    asm volatile("cp.async.commit_group;" ::: "memory");
}

// B tile [BK x BN] (normal orientation) -> regs; chunk f: n = f&63, c = f>>6 (0..15)
__device__ __forceinline__ void ldgB(const float* __restrict__ B,
                                     int bn, int kt, float4* v, int tid) {
#pragma unroll
    for (int i = 0; i < 8; i++) {
        int f = tid + i * NTH;
        int n = f & 63, c = f >> 6;
        const float* p = B + (size_t)(kt * BK + 4 * c) * N_DIM + bn + n;
        v[i].x = p[0];
        v[i].y = p[N_DIM];
        v[i].z = p[2 * N_DIM];
        v[i].w = p[3 * N_DIM];
    }
}
__device__ __forceinline__ void stsB(uint32_t Bb, const float4* v, int tid) {
#pragma unroll
    for (int i = 0; i < 8; i++) {
        int f = tid + i * NTH;
        int n = f & 63, c = f >> 6;
        uint32_t dst = Bb + n * 256 + ((c ^ (n & 7)) << 4);
        asm volatile("st.shared.v4.b32 [%0], {%1, %2, %3, %4};"
                     :: "r"(dst),
                        "r"(__float_as_uint(v[i].x)), "r"(__float_as_uint(v[i].y)),
                        "r"(__float_as_uint(v[i].z)), "r"(__float_as_uint(v[i].w))
                     : "memory");
    }
}

// z=0: C = bs*Bias + Bias2 + A@B (round if rnd). z=1: C1 = A1@B1 (rounded).
__global__ void __launch_bounds__(NTH, 3)
gemm_nn(const float* __restrict__ A, const float* __restrict__ B,
        const float* __restrict__ Bias, float bs,
        const float* __restrict__ Bias2,
        float* __restrict__ C, int rnd,
        const float* __restrict__ A1, const float* __restrict__ B1,
        float* __restrict__ C1)
{
    if (blockIdx.z) {
        A = A1; B = B1; C = C1;
        Bias = nullptr; Bias2 = nullptr; rnd = 1;
    }
    extern __shared__ char smem[];
    const uint32_t sb = smem_u32(smem);
    const int tid = threadIdx.x, lid = tid & 31, wid = tid >> 5;
    const int wm = (wid & 1) * 32, wn = (wid >> 1) * 32;   // 2x2 warps, 32x32 tiles
    const int bm = blockIdx.y * BM, bn = blockIdx.x * BN;

    float d[2][4][4];
#pragma unroll
    for (int i = 0; i < 2; i++)
#pragma unroll
        for (int j = 0; j < 4; j++)
#pragma unroll
            for (int k = 0; k < 4; k++) d[i][j][k] = 0.0f;

    const int sub = lid >> 3;
    const int r8  = lid & 7;
    const int a_row = wm + (sub & 1) * 8 + r8;
    const int a_chs = (sub >> 1);
    const int b_row = wn + (sub >> 1) * 8 + r8;
    const int b_chs = (sub & 1);

    float4 bv[8];
    issueA(A, bm, 0, sb, tid);
    ldgB(B, bn, 0, bv, tid);

    for (int kt = 0; kt < NKT; kt++) {
        const uint32_t buf = sb + (kt & 1) * STAGE;
        stsB(buf + ABYTES, bv, tid);
        if (kt + 1 < NKT) {
            issueA(A, bm, kt + 1, sb + ((kt + 1) & 1) * STAGE, tid);
            ldgB(B, bn, kt + 1, bv, tid);
            asm volatile("cp.async.wait_group 1;" ::: "memory");
        } else {
            asm volatile("cp.async.wait_group 0;" ::: "memory");
        }
        __syncthreads();

        const uint32_t Ab = buf;
        const uint32_t Bb = buf + ABYTES;
#pragma unroll
        for (int ks = 0; ks < 8; ks++) {
            uint32_t a[2][4], b[2][4];
#pragma unroll
            for (int mf = 0; mf < 2; mf++) {
                int row = a_row + mf * 16;
                int ch = ks * 2 + a_chs;
                ldm_x4(a[mf], Ab + row * 256 + ((ch ^ (row & 7)) << 4));
            }
#pragma unroll
            for (int j = 0; j < 2; j++) {
                int row = b_row + j * 16;
                int ch = ks * 2 + b_chs;
                ldm_x4(b[j], Bb + row * 256 + ((ch ^ (row & 7)) << 4));
            }
#pragma unroll
            for (int mf = 0; mf < 2; mf++)
#pragma unroll
                for (int nf = 0; nf < 4; nf++)
                    mma_tf32(d[mf][nf], a[mf],
                             b[nf >> 1][(nf & 1) * 2], b[nf >> 1][(nf & 1) * 2 + 1]);
        }
        __syncthreads();
    }

    const int g = lid >> 2, t = lid & 3;
#pragma unroll
    for (int mf = 0; mf < 2; mf++) {
#pragma unroll
        for (int nf = 0; nf < 4; nf++) {
            int row0 = bm + wm + mf * 16 + g;
            int col = bn + wn + nf * 8 + 2 * t;
            size_t off = (size_t)row0 * N_DIM + col;
            float2 o0 = make_float2(d[mf][nf][0], d[mf][nf][1]);
            float2 o1 = make_float2(d[mf][nf][2], d[mf][nf][3]);
            if (Bias) {
                const float* bp0 = Bias + off;
                float2 t0 = *reinterpret_cast<const float2*>(bp0);
                float2 t1v = *reinterpret_cast<const float2*>(bp0 + 8 * N_DIM);
                o0.x = fmaf(bs, t0.x, o0.x);
                o0.y = fmaf(bs, t0.y, o0.y);
                o1.x = fmaf(bs, t1v.x, o1.x);
                o1.y = fmaf(bs, t1v.y, o1.y);
            }
            if (Bias2) {
                const float* b2 = Bias2 + off;
                float2 u0 = *reinterpret_cast<const float2*>(b2);
                float2 u1 = *reinterpret_cast<const float2*>(b2 + 8 * N_DIM);
                o0.x += u0.x; o0.y += u0.y;
                o1.x += u1.x; o1.y += u1.y;
            }
            if (rnd) {
                o0.x = to_tf32(o0.x); o0.y = to_tf32(o0.y);
                o1.x = to_tf32(o1.x); o1.y = to_tf32(o1.y);
            }
            float* cp0 = C + off;
            *reinterpret_cast<float2*>(cp0) = o0;
            *reinterpret_cast<float2*>(cp0 + 8 * N_DIM) = o1;
        }
    }
}

// grid (1024, 2): y=0 rounds t1 -> o1, y=1 rounds t2 -> o2
__global__ void __launch_bounds__(256)
cvt2_k(const float* __restrict__ i1, const float* __restrict__ i2,
       float* __restrict__ o1, float* __restrict__ o2) {
    const float* in = blockIdx.y ? i2 : i1;
    float* out = blockIdx.y ? o2 : o1;
    int i = (blockIdx.x * 256 + threadIdx.x) * 4;
    float4 v = *reinterpret_cast<const float4*>(in + i);
    v.x = to_tf32(v.x); v.y = to_tf32(v.y);
    v.z = to_tf32(v.z); v.w = to_tf32(v.w);
    *reinterpret_cast<float4*>(out + i) = v;
}

extern "C" void kernel_launch(void* const* d_in, const int* in_sizes, int n_in,
                              void* d_out, int out_size)
{
    const float* t1 = (const float*)d_in[0];
    const float* t2 = (const float*)d_in[1];
    float* out = (float*)d_out;

    float *t1c, *t2c, *sA, *sB, *pA, *pB, *U;
    cudaGetSymbolAddress((void**)&t1c, g_t1c);
    cudaGetSymbolAddress((void**)&t2c, g_t2c);
    cudaGetSymbolAddress((void**)&sA, g_sA);
    cudaGetSymbolAddress((void**)&sB, g_sB);
    cudaGetSymbolAddress((void**)&pA, g_pA);
    cudaGetSymbolAddress((void**)&pB, g_pB);
    cudaGetSymbolAddress((void**)&U, g_U);

    cudaFuncSetAttribute(gemm_nn, cudaFuncAttributeMaxDynamicSharedMemorySize, SMEM_TOTAL);

    cvt2_k<<<dim3(N_DIM * N_DIM / 1024, 2), 256>>>(t1, t2, t1c, t2c);

    dim3 g1(N_DIM / BN, N_DIM / BM, 1);   // (16,16) = 256 CTAs
    dim3 g2(N_DIM / BN, N_DIM / BM, 2);   // merged: 512 CTAs

    // Pair map: X' = C + T X T, T = t2, C = t1 + t1@t2.
    // out ≈ S_8 + t1 (series tail ~3e-5 rel).  Doubling: U=P@S; S'=S+U@P; P'=P@P.
    //
    // L1: S1 = t1 + t1c@t2c -> sA  ||  P2 = t2c@t2c -> pA
    gemm_nn<<<g2, NTH, SMEM_TOTAL>>>(t1c, t2c, t1, 1.0f, nullptr, sA, 1,
                                     t2c, t2c, pA);
    // L2: U = t2c@S1
    gemm_nn<<<g1, NTH, SMEM_TOTAL>>>(t2c, sA, nullptr, 0.0f, nullptr, U, 1,
                                     nullptr, nullptr, nullptr);
    // L3: S2 = S1 + U@t2c -> sB
    gemm_nn<<<g1, NTH, SMEM_TOTAL>>>(U, t2c, sA, 1.0f, nullptr, sB, 1,
                                     nullptr, nullptr, nullptr);
    // L4: U2 = P2@S2 -> U  ||  P4 = P2@P2 -> pB
    gemm_nn<<<g2, NTH, SMEM_TOTAL>>>(pA, sB, nullptr, 0.0f, nullptr, U, 1,
                                     pA, pA, pB);
    // L5: S4 = S2 + U2@P2 -> sA
    gemm_nn<<<g1, NTH, SMEM_TOTAL>>>(U, pA, sB, 1.0f, nullptr, sA, 1,
                                     nullptr, nullptr, nullptr);
    // L6: U3 = P4@S4 -> U
    gemm_nn<<<g1, NTH, SMEM_TOTAL>>>(pB, sA, nullptr, 0.0f, nullptr, U, 1,
                                     nullptr, nullptr, nullptr);
    // L7: out = S4 + U3@P4 + t1  (fp32, no rounding)
    gemm_nn<<<g1, NTH, SMEM_TOTAL>>>(U, pB, sA, 1.0f, t1, out, 0,
                                     nullptr, nullptr, nullptr);
}

// round 8
// speedup vs baseline: 1.1961x; 1.0982x over previous
#include <cuda_runtime.h>
#include <cstdint>

#define N_DIM 1024
#define BM 128
#define BN 64
#define BK 64
#define NKT_H 8                    // k-iterations per half (each half covers K=512)
#define NTH 512                    // 16 warps: warps 0-7 = half 0, 8-15 = half 1

#define ABYTES (BM * BK * 4)       // 32768
#define BBYTES (BN * BK * 4)       // 16384
#define STAGE  (ABYTES + BBYTES)   // 49152
#define HALF_SMEM (2 * STAGE)      // 98304 per half (double-buffered)
#define SMEM_TOTAL (2 * HALF_SMEM) // 196608

// scratch (allocation-free rules)
__device__ float g_t1c[N_DIM * N_DIM];   // tf32(t1)
__device__ float g_t2c[N_DIM * N_DIM];   // tf32(t2) = P_1
__device__ float g_sA [N_DIM * N_DIM];
__device__ float g_sB [N_DIM * N_DIM];
__device__ float g_pA [N_DIM * N_DIM];
__device__ float g_pB [N_DIM * N_DIM];
__device__ float g_U  [N_DIM * N_DIM];

__device__ __forceinline__ uint32_t smem_u32(const void* p) {
    uint32_t r;
    asm("{ .reg .u64 t; cvta.to.shared.u64 t, %1; cvt.u32.u64 %0, t; }" : "=r"(r) : "l"(p));
    return r;
}
__device__ __forceinline__ float to_tf32(float x) {
    uint32_t u;
    asm("cvt.rna.tf32.f32 %0, %1;" : "=r"(u) : "f"(x));
    return __uint_as_float(u);
}
__device__ __forceinline__ void cp16(uint32_t dst, const float* src) {
    asm volatile("cp.async.cg.shared.global [%0], [%1], 16;"
                 :: "r"(dst), "l"(src) : "memory");
}
__device__ __forceinline__ void ldm_x4(uint32_t* r, uint32_t addr) {
    asm volatile("ldmatrix.sync.aligned.m8n8.x4.shared.b16 {%0,%1,%2,%3}, [%4];"
                 : "=r"(r[0]), "=r"(r[1]), "=r"(r[2]), "=r"(r[3]) : "r"(addr));
}
__device__ __forceinline__ void mma_tf32(float* d, const uint32_t* a,
                                         uint32_t b0, uint32_t b1) {
    asm volatile(
        "mma.sync.aligned.m16n8k8.row.col.f32.tf32.tf32.f32 "
        "{%0,%1,%2,%3}, {%4,%5,%6,%7}, {%8,%9}, {%0,%1,%2,%3};"
        : "+f"(d[0]), "+f"(d[1]), "+f"(d[2]), "+f"(d[3])
        : "r"(a[0]), "r"(a[1]), "r"(a[2]), "r"(a[3]), "r"(b0), "r"(b1));
}

// A tile [BM x BK] via cp.async, K-major swizzled smem (row = m, 256B rows, 16 chunks)
// htid in [0,256), 2048 chunks per tile -> 8 per thread.
__device__ __forceinline__ void issueA(const float* __restrict__ A,
                                       int bm, int k0, uint32_t base, int htid) {
#pragma unroll
    for (int i = 0; i < 8; i++) {
        int f = htid + i * 256;
        int row = f >> 4, c = f & 15;
        uint32_t dst = base + row * 256 + ((c ^ (row & 7)) << 4);
        cp16(dst, A + (size_t)(bm + row) * N_DIM + k0 + c * 4);
    }
    asm volatile("cp.async.commit_group;" ::: "memory");
}

// B tile [BK x BN] (normal orientation) -> regs; 1024 chunks -> 4 per thread
__device__ __forceinline__ void ldgB(const float* __restrict__ B,
                                     int bn, int k0, float4* v, int htid) {
#pragma unroll
    for (int i = 0; i < 4; i++) {
        int f = htid + i * 256;
        int n = f & 63, c = f >> 6;             // c in [0,16)
        const float* p = B + (size_t)(k0 + 4 * c) * N_DIM + bn + n;
        v[i].x = p[0];
        v[i].y = p[N_DIM];
        v[i].z = p[2 * N_DIM];
        v[i].w = p[3 * N_DIM];
    }
}
__device__ __forceinline__ void stsB(uint32_t Bb, const float4* v, int htid) {
#pragma unroll
    for (int i = 0; i < 4; i++) {
        int f = htid + i * 256;
        int n = f & 63, c = f >> 6;
        uint32_t dst = Bb + n * 256 + ((c ^ (n & 7)) << 4);
        asm volatile("st.shared.v4.b32 [%0], {%1, %2, %3, %4};"
                     :: "r"(dst),
                        "r"(__float_as_uint(v[i].x)), "r"(__float_as_uint(v[i].y)),
                        "r"(__float_as_uint(v[i].z)), "r"(__float_as_uint(v[i].w))
                     : "memory");
    }
}

// z=0: C = bs*Bias + Bias2 + A@B (round if rnd). z=1: C1 = A1@B1 (rounded).
// In-CTA split-K: warps 0-7 do K[0:512], warps 8-15 do K[512:1024]; exact f32 sum.
__global__ void __launch_bounds__(NTH, 1)
gemm_nn(const float* __restrict__ A, const float* __restrict__ B,
        const float* __restrict__ Bias, float bs,
        const float* __restrict__ Bias2,
        float* __restrict__ C, int rnd,
        const float* __restrict__ A1, const float* __restrict__ B1,
        float* __restrict__ C1)
{
    if (blockIdx.z) {
        A = A1; B = B1; C = C1;
        Bias = nullptr; Bias2 = nullptr; rnd = 1;
    }
    extern __shared__ char smem[];
    const uint32_t sb = smem_u32(smem);
    const int tid = threadIdx.x, lid = tid & 31, wid = tid >> 5;
    const int half = wid >> 3;                 // k-half
    const int hw = wid & 7;                    // warp within half
    const int htid = tid & 255;                // thread within half
    const int wm = (hw & 3) * 32, wn = (hw >> 1 & 2) * 32;  // careful: hw>>2 in [0,1]
    const int wn2 = (hw >> 2) * 32;
    const int bm = blockIdx.y * BM, bn = blockIdx.x * BN;
    const int kbase = half * 512;
    const uint32_t hbase = sb + half * HALF_SMEM;

    float d[2][4][4];
#pragma unroll
    for (int i = 0; i < 2; i++)
#pragma unroll
        for (int j = 0; j < 4; j++)
#pragma unroll
            for (int k = 0; k < 4; k++) d[i][j][k] = 0.0f;

    const int sub = lid >> 3;
    const int r8  = lid & 7;
    const int a_row = wm + (sub & 1) * 8 + r8;
    const int a_chs = (sub >> 1);
    const int b_row = wn2 + (sub >> 1) * 8 + r8;
    const int b_chs = (sub & 1);

    float4 bv[4];
    issueA(A, bm, kbase, hbase, htid);
    ldgB(B, bn, kbase, bv, htid);

    for (int kt = 0; kt < NKT_H; kt++) {
        const uint32_t buf = hbase + (kt & 1) * STAGE;
        stsB(buf + ABYTES, bv, htid);
        if (kt + 1 < NKT_H) {
            issueA(A, bm, kbase + (kt + 1) * BK, hbase + ((kt + 1) & 1) * STAGE, htid);
            ldgB(B, bn, kbase + (kt + 1) * BK, bv, htid);
            asm volatile("cp.async.wait_group 1;" ::: "memory");
        } else {
            asm volatile("cp.async.wait_group 0;" ::: "memory");
        }
        __syncthreads();

        const uint32_t Ab = buf;
        const uint32_t Bb = buf + ABYTES;
#pragma unroll
        for (int ks = 0; ks < 8; ks++) {
            uint32_t a[2][4], b[2][4];
#pragma unroll
            for (int mf = 0; mf < 2; mf++) {
                int row = a_row + mf * 16;
                int ch = ks * 2 + a_chs;
                ldm_x4(a[mf], Ab + row * 256 + ((ch ^ (row & 7)) << 4));
            }
#pragma unroll
            for (int j = 0; j < 2; j++) {
                int row = b_row + j * 16;
                int ch = ks * 2 + b_chs;
                ldm_x4(b[j], Bb + row * 256 + ((ch ^ (row & 7)) << 4));
            }
#pragma unroll
            for (int mf = 0; mf < 2; mf++)
#pragma unroll
                for (int nf = 0; nf < 4; nf++)
                    mma_tf32(d[mf][nf], a[mf],
                             b[nf >> 1][(nf & 1) * 2], b[nf >> 1][(nf & 1) * 2 + 1]);
        }
        __syncthreads();
    }

    // ---- cross-half reduction: half 1 -> smem, half 0 adds ----
    if (half) {
#pragma unroll
        for (int mf = 0; mf < 2; mf++)
#pragma unroll
            for (int nf = 0; nf < 4; nf++) {
                int i = mf * 4 + nf;
                uint32_t dst = sb + (uint32_t)(i * 256 + htid) * 16;
                asm volatile("st.shared.v4.b32 [%0], {%1, %2, %3, %4};"
                             :: "r"(dst),
                                "r"(__float_as_uint(d[mf][nf][0])),
                                "r"(__float_as_uint(d[mf][nf][1])),
                                "r"(__float_as_uint(d[mf][nf][2])),
                                "r"(__float_as_uint(d[mf][nf][3]))
                             : "memory");
            }
    }
    __syncthreads();
    if (half) return;

#pragma unroll
    for (int mf = 0; mf < 2; mf++)
#pragma unroll
        for (int nf = 0; nf < 4; nf++) {
            int i = mf * 4 + nf;
            uint32_t src = sb + (uint32_t)(i * 256 + htid) * 16;
            uint32_t p0, p1, p2, p3;
            asm volatile("ld.shared.v4.b32 {%0,%1,%2,%3}, [%4];"
                         : "=r"(p0), "=r"(p1), "=r"(p2), "=r"(p3) : "r"(src));
            d[mf][nf][0] += __uint_as_float(p0);
            d[mf][nf][1] += __uint_as_float(p1);
            d[mf][nf][2] += __uint_as_float(p2);
            d[mf][nf][3] += __uint_as_float(p3);
        }

    const int g = lid >> 2, t = lid & 3;
#pragma unroll
    for (int mf = 0; mf < 2; mf++) {
#pragma unroll
        for (int nf = 0; nf < 4; nf++) {
            int row0 = bm + wm + mf * 16 + g;
            int col = bn + wn2 + nf * 8 + 2 * t;
            size_t off = (size_t)row0 * N_DIM + col;
            float2 o0 = make_float2(d[mf][nf][0], d[mf][nf][1]);
            float2 o1 = make_float2(d[mf][nf][2], d[mf][nf][3]);
            if (Bias) {
                const float* bp0 = Bias + off;
                float2 t0 = *reinterpret_cast<const float2*>(bp0);
                float2 t1v = *reinterpret_cast<const float2*>(bp0 + 8 * N_DIM);
                o0.x = fmaf(bs, t0.x, o0.x);
                o0.y = fmaf(bs, t0.y, o0.y);
                o1.x = fmaf(bs, t1v.x, o1.x);
                o1.y = fmaf(bs, t1v.y, o1.y);
            }
            if (Bias2) {
                const float* b2 = Bias2 + off;
                float2 u0 = *reinterpret_cast<const float2*>(b2);
                float2 u1 = *reinterpret_cast<const float2*>(b2 + 8 * N_DIM);
                o0.x += u0.x; o0.y += u0.y;
                o1.x += u1.x; o1.y += u1.y;
            }
            if (rnd) {
                o0.x = to_tf32(o0.x); o0.y = to_tf32(o0.y);
                o1.x = to_tf32(o1.x); o1.y = to_tf32(o1.y);
            }
            float* cp0 = C + off;
            *reinterpret_cast<float2*>(cp0) = o0;
            *reinterpret_cast<float2*>(cp0 + 8 * N_DIM) = o1;
        }
    }
}

// grid (1024, 2): y=0 rounds t1 -> o1, y=1 rounds t2 -> o2
__global__ void __launch_bounds__(256)
cvt2_k(const float* __restrict__ i1, const float* __restrict__ i2,
       float* __restrict__ o1, float* __restrict__ o2) {
    const float* in = blockIdx.y ? i2 : i1;
    float* out = blockIdx.y ? o2 : o1;
    int i = (blockIdx.x * 256 + threadIdx.x) * 4;
    float4 v = *reinterpret_cast<const float4*>(in + i);
    v.x = to_tf32(v.x); v.y = to_tf32(v.y);
    v.z = to_tf32(v.z); v.w = to_tf32(v.w);
    *reinterpret_cast<float4*>(out + i) = v;
}

extern "C" void kernel_launch(void* const* d_in, const int* in_sizes, int n_in,
                              void* d_out, int out_size)
{
    const float* t1 = (const float*)d_in[0];
    const float* t2 = (const float*)d_in[1];
    float* out = (float*)d_out;

    float *t1c, *t2c, *sA, *sB, *pA, *pB, *U;
    cudaGetSymbolAddress((void**)&t1c, g_t1c);
    cudaGetSymbolAddress((void**)&t2c, g_t2c);
    cudaGetSymbolAddress((void**)&sA, g_sA);
    cudaGetSymbolAddress((void**)&sB, g_sB);
    cudaGetSymbolAddress((void**)&pA, g_pA);
    cudaGetSymbolAddress((void**)&pB, g_pB);
    cudaGetSymbolAddress((void**)&U, g_U);

    cudaFuncSetAttribute(gemm_nn, cudaFuncAttributeMaxDynamicSharedMemorySize, SMEM_TOTAL);

    cvt2_k<<<dim3(N_DIM * N_DIM / 1024, 2), 256>>>(t1, t2, t1c, t2c);

    dim3 g1(N_DIM / BN, N_DIM / BM, 1);   // (16,8) = 128 CTAs
    dim3 g2(N_DIM / BN, N_DIM / BM, 2);   // merged pair: 256 CTAs

    // Pair map: X' = C + T X T, T = t2, C = t1 + t1@t2.
    // out ≈ S_8 + t1 (series tail ~3e-5 rel).  Doubling: U=P@S; S'=S+U@P; P'=P@P.
    //
    // L1: S1 = t1 + t1c@t2c -> sA  ||  P2 = t2c@t2c -> pA
    gemm_nn<<<g2, NTH, SMEM_TOTAL>>>(t1c, t2c, t1, 1.0f, nullptr, sA, 1,
                                     t2c, t2c, pA);
    // L2: U = t2c@S1
    gemm_nn<<<g1, NTH, SMEM_TOTAL>>>(t2c, sA, nullptr, 0.0f, nullptr, U, 1,
                                     nullptr, nullptr, nullptr);
    // L3: S2 = S1 + U@t2c -> sB
    gemm_nn<<<g1, NTH, SMEM_TOTAL>>>(U, t2c, sA, 1.0f, nullptr, sB, 1,
                                     nullptr, nullptr, nullptr);
    // L4: U2 = P2@S2 -> U  ||  P4 = P2@P2 -> pB
    gemm_nn<<<g2, NTH, SMEM_TOTAL>>>(pA, sB, nullptr, 0.0f, nullptr, U, 1,
                                     pA, pA, pB);
    // L5: S4 = S2 + U2@P2 -> sA
    gemm_nn<<<g1, NTH, SMEM_TOTAL>>>(U, pA, sB, 1.0f, nullptr, sA, 1,
                                     nullptr, nullptr, nullptr);
    // L6: U3 = P4@S4 -> U
    gemm_nn<<<g1, NTH, SMEM_TOTAL>>>(pB, sA, nullptr, 0.0f, nullptr, U, 1,
                                     nullptr, nullptr, nullptr);
    // L7: out = S4 + U3@P4 + t1  (fp32, no rounding)
    gemm_nn<<<g1, NTH, SMEM_TOTAL>>>(U, pB, sA, 1.0f, t1, out, 0,
                                     nullptr, nullptr, nullptr);
}

// round 9
// speedup vs baseline: 1.2119x; 1.0132x over previous
#include <cuda_runtime.h>
#include <cstdint>

#define N_DIM 1024
#define BM 128
#define BN 64
#define BK 64
#define NKT_H 8                    // k-iterations per half (each half covers K=512)
#define NTH 512                    // 16 warps: warps 0-7 = half 0, 8-15 = half 1

#define ABYTES (BM * BK * 4)       // 32768
#define BROW   288                 // 64 B-floats (256B) + 32B pad -> bank = (8k+n)%32
#define BBYTES (BK * BROW)         // 18432
#define STAGE  (ABYTES + BBYTES)   // 51200
#define HALF_SMEM (2 * STAGE)      // 102400
#define SMEM_TOTAL (2 * HALF_SMEM) // 204800

// scratch (allocation-free rules)
__device__ float g_t1c[N_DIM * N_DIM];   // tf32(t1)
__device__ float g_t2c[N_DIM * N_DIM];   // tf32(t2) = P_1
__device__ float g_sA [N_DIM * N_DIM];
__device__ float g_sB [N_DIM * N_DIM];
__device__ float g_pA [N_DIM * N_DIM];
__device__ float g_pB [N_DIM * N_DIM];
__device__ float g_U  [N_DIM * N_DIM];

__device__ __forceinline__ uint32_t smem_u32(const void* p) {
    uint32_t r;
    asm("{ .reg .u64 t; cvta.to.shared.u64 t, %1; cvt.u32.u64 %0, t; }" : "=r"(r) : "l"(p));
    return r;
}
__device__ __forceinline__ float to_tf32(float x) {
    uint32_t u;
    asm("cvt.rna.tf32.f32 %0, %1;" : "=r"(u) : "f"(x));
    return __uint_as_float(u);
}
__device__ __forceinline__ void cp16(uint32_t dst, const float* src) {
    asm volatile("cp.async.cg.shared.global [%0], [%1], 16;"
                 :: "r"(dst), "l"(src) : "memory");
}
__device__ __forceinline__ void ldm_x4(uint32_t* r, uint32_t addr) {
    asm volatile("ldmatrix.sync.aligned.m8n8.x4.shared.b16 {%0,%1,%2,%3}, [%4];"
                 : "=r"(r[0]), "=r"(r[1]), "=r"(r[2]), "=r"(r[3]) : "r"(addr));
}
__device__ __forceinline__ uint32_t lds32(uint32_t addr) {
    uint32_t v;
    asm volatile("ld.shared.b32 %0, [%1];" : "=r"(v) : "r"(addr));
    return v;
}
__device__ __forceinline__ void mma_tf32(float* d, const uint32_t* a,
                                         uint32_t b0, uint32_t b1) {
    asm volatile(
        "mma.sync.aligned.m16n8k8.row.col.f32.tf32.tf32.f32 "
        "{%0,%1,%2,%3}, {%4,%5,%6,%7}, {%8,%9}, {%0,%1,%2,%3};"
        : "+f"(d[0]), "+f"(d[1]), "+f"(d[2]), "+f"(d[3])
        : "r"(a[0]), "r"(a[1]), "r"(a[2]), "r"(a[3]), "r"(b0), "r"(b1));
}

// A tile [BM x BK] via cp.async, K-major swizzled smem (row = m, 256B rows, 16 chunks)
__device__ __forceinline__ void issueA(const float* __restrict__ A,
                                       int bm, int k0, uint32_t base, int htid) {
#pragma unroll
    for (int i = 0; i < 8; i++) {
        int f = htid + i * 256;
        int row = f >> 4, c = f & 15;
        uint32_t dst = base + row * 256 + ((c ^ (row & 7)) << 4);
        cp16(dst, A + (size_t)(bm + row) * N_DIM + k0 + c * 4);
    }
}

// B tile [BK x BN] via cp.async in NATURAL layout (row = k, 256B data + 32B pad)
__device__ __forceinline__ void issueB(const float* __restrict__ B,
                                       int bn, int k0, uint32_t base, int htid) {
#pragma unroll
    for (int i = 0; i < 4; i++) {
        int f = htid + i * 256;              // 1024 chunks
        int k = f >> 4, c = f & 15;
        uint32_t dst = base + k * BROW + c * 16;
        cp16(dst, B + (size_t)(k0 + k) * N_DIM + bn + c * 4);
    }
}

// z=0: C = bs*Bias + Bias2 + A@B (round if rnd). z=1: C1 = A1@B1 (rounded).
// In-CTA split-K: warps 0-7 do K[0:512], warps 8-15 do K[512:1024]; exact f32 sum.
__global__ void __launch_bounds__(NTH, 1)
gemm_nn(const float* __restrict__ A, const float* __restrict__ B,
        const float* __restrict__ Bias, float bs,
        const float* __restrict__ Bias2,
        float* __restrict__ C, int rnd,
        const float* __restrict__ A1, const float* __restrict__ B1,
        float* __restrict__ C1)
{
    if (blockIdx.z) {
        A = A1; B = B1; C = C1;
        Bias = nullptr; Bias2 = nullptr; rnd = 1;
    }
    extern __shared__ char smem[];
    const uint32_t sb = smem_u32(smem);
    const int tid = threadIdx.x, lid = tid & 31, wid = tid >> 5;
    const int half = wid >> 3;                 // k-half
    const int hw = wid & 7;                    // warp within half
    const int htid = tid & 255;                // thread within half
    const int wm = (hw & 3) * 32;
    const int wn2 = (hw >> 2) * 32;
    const int bm = blockIdx.y * BM, bn = blockIdx.x * BN;
    const int kbase = half * 512;
    const uint32_t hbase = sb + half * HALF_SMEM;

    float d[2][4][4];
#pragma unroll
    for (int i = 0; i < 2; i++)
#pragma unroll
        for (int j = 0; j < 4; j++)
#pragma unroll
            for (int k = 0; k < 4; k++) d[i][j][k] = 0.0f;

    const int sub = lid >> 3;
    const int r8  = lid & 7;
    const int a_row = wm + (sub & 1) * 8 + r8;
    const int a_chs = (sub >> 1);
    // B fragment (m16n8k8 tf32): b0 at (k = lid%4, n = lid/4), b1 at k+4
    const uint32_t b_off = (uint32_t)((lid & 3) * BROW + (wn2 + (lid >> 2)) * 4);

    issueA(A, bm, kbase, hbase, htid);
    issueB(B, bn, kbase, hbase + ABYTES, htid);
    asm volatile("cp.async.commit_group;" ::: "memory");

    for (int kt = 0; kt < NKT_H; kt++) {
        const uint32_t buf = hbase + (kt & 1) * STAGE;
        if (kt + 1 < NKT_H) {
            const uint32_t nbuf = hbase + ((kt + 1) & 1) * STAGE;
            issueA(A, bm, kbase + (kt + 1) * BK, nbuf, htid);
            issueB(B, bn, kbase + (kt + 1) * BK, nbuf + ABYTES, htid);
            asm volatile("cp.async.commit_group;" ::: "memory");
            asm volatile("cp.async.wait_group 1;" ::: "memory");
        } else {
            asm volatile("cp.async.wait_group 0;" ::: "memory");
        }
        __syncthreads();

        const uint32_t Ab = buf;
        const uint32_t Bb = buf + ABYTES;
#pragma unroll
        for (int ks = 0; ks < 8; ks++) {
            uint32_t a[2][4];
#pragma unroll
            for (int mf = 0; mf < 2; mf++) {
                int row = a_row + mf * 16;
                int ch = ks * 2 + a_chs;
                ldm_x4(a[mf], Ab + row * 256 + ((ch ^ (row & 7)) << 4));
            }
            const uint32_t bbase = Bb + ks * 8 * BROW + b_off;
            uint32_t b0[4], b1[4];
#pragma unroll
            for (int nf = 0; nf < 4; nf++) {
                b0[nf] = lds32(bbase + nf * 32);
                b1[nf] = lds32(bbase + 4 * BROW + nf * 32);
            }
#pragma unroll
            for (int mf = 0; mf < 2; mf++)
#pragma unroll
                for (int nf = 0; nf < 4; nf++)
                    mma_tf32(d[mf][nf], a[mf], b0[nf], b1[nf]);
        }
        __syncthreads();
    }

    // ---- cross-half reduction: half 1 -> smem, half 0 adds (exact f32) ----
    if (half) {
#pragma unroll
        for (int mf = 0; mf < 2; mf++)
#pragma unroll
            for (int nf = 0; nf < 4; nf++) {
                int i = mf * 4 + nf;
                uint32_t dst = sb + (uint32_t)(i * 256 + htid) * 16;
                asm volatile("st.shared.v4.b32 [%0], {%1, %2, %3, %4};"
                             :: "r"(dst),
                                "r"(__float_as_uint(d[mf][nf][0])),
                                "r"(__float_as_uint(d[mf][nf][1])),
                                "r"(__float_as_uint(d[mf][nf][2])),
                                "r"(__float_as_uint(d[mf][nf][3]))
                             : "memory");
            }
    }
    __syncthreads();
    if (half) return;

#pragma unroll
    for (int mf = 0; mf < 2; mf++)
#pragma unroll
        for (int nf = 0; nf < 4; nf++) {
            int i = mf * 4 + nf;
            uint32_t src = sb + (uint32_t)(i * 256 + htid) * 16;
            uint32_t p0, p1, p2, p3;
            asm volatile("ld.shared.v4.b32 {%0,%1,%2,%3}, [%4];"
                         : "=r"(p0), "=r"(p1), "=r"(p2), "=r"(p3) : "r"(src));
            d[mf][nf][0] += __uint_as_float(p0);
            d[mf][nf][1] += __uint_as_float(p1);
            d[mf][nf][2] += __uint_as_float(p2);
            d[mf][nf][3] += __uint_as_float(p3);
        }

    const int g = lid >> 2, t = lid & 3;
#pragma unroll
    for (int mf = 0; mf < 2; mf++) {
#pragma unroll
        for (int nf = 0; nf < 4; nf++) {
            int row0 = bm + wm + mf * 16 + g;
            int col = bn + wn2 + nf * 8 + 2 * t;
            size_t off = (size_t)row0 * N_DIM + col;
            float2 o0 = make_float2(d[mf][nf][0], d[mf][nf][1]);
            float2 o1 = make_float2(d[mf][nf][2], d[mf][nf][3]);
            if (Bias) {
                const float* bp0 = Bias + off;
                float2 t0 = *reinterpret_cast<const float2*>(bp0);
                float2 t1v = *reinterpret_cast<const float2*>(bp0 + 8 * N_DIM);
                o0.x = fmaf(bs, t0.x, o0.x);
                o0.y = fmaf(bs, t0.y, o0.y);
                o1.x = fmaf(bs, t1v.x, o1.x);
                o1.y = fmaf(bs, t1v.y, o1.y);
            }
            if (Bias2) {
                const float* b2 = Bias2 + off;
                float2 u0 = *reinterpret_cast<const float2*>(b2);
                float2 u1 = *reinterpret_cast<const float2*>(b2 + 8 * N_DIM);
                o0.x += u0.x; o0.y += u0.y;
                o1.x += u1.x; o1.y += u1.y;
            }
            if (rnd) {
                o0.x = to_tf32(o0.x); o0.y = to_tf32(o0.y);
                o1.x = to_tf32(o1.x); o1.y = to_tf32(o1.y);
            }
            float* cp0 = C + off;
            *reinterpret_cast<float2*>(cp0) = o0;
            *reinterpret_cast<float2*>(cp0 + 8 * N_DIM) = o1;
        }
    }
}

// grid (1024, 2): y=0 rounds t1 -> o1, y=1 rounds t2 -> o2
__global__ void __launch_bounds__(256)
cvt2_k(const float* __restrict__ i1, const float* __restrict__ i2,
       float* __restrict__ o1, float* __restrict__ o2) {
    const float* in = blockIdx.y ? i2 : i1;
    float* out = blockIdx.y ? o2 : o1;
    int i = (blockIdx.x * 256 + threadIdx.x) * 4;
    float4 v = *reinterpret_cast<const float4*>(in + i);
    v.x = to_tf32(v.x); v.y = to_tf32(v.y);
    v.z = to_tf32(v.z); v.w = to_tf32(v.w);
    *reinterpret_cast<float4*>(out + i) = v;
}

extern "C" void kernel_launch(void* const* d_in, const int* in_sizes, int n_in,
                              void* d_out, int out_size)
{
    const float* t1 = (const float*)d_in[0];
    const float* t2 = (const float*)d_in[1];
    float* out = (float*)d_out;

    float *t1c, *t2c, *sA, *sB, *pA, *pB, *U;
    cudaGetSymbolAddress((void**)&t1c, g_t1c);
    cudaGetSymbolAddress((void**)&t2c, g_t2c);
    cudaGetSymbolAddress((void**)&sA, g_sA);
    cudaGetSymbolAddress((void**)&sB, g_sB);
    cudaGetSymbolAddress((void**)&pA, g_pA);
    cudaGetSymbolAddress((void**)&pB, g_pB);
    cudaGetSymbolAddress((void**)&U, g_U);

    cudaFuncSetAttribute(gemm_nn, cudaFuncAttributeMaxDynamicSharedMemorySize, SMEM_TOTAL);

    cvt2_k<<<dim3(N_DIM * N_DIM / 1024, 2), 256>>>(t1, t2, t1c, t2c);

    dim3 g1(N_DIM / BN, N_DIM / BM, 1);   // (16,8) = 128 CTAs
    dim3 g2(N_DIM / BN, N_DIM / BM, 2);   // merged pair: 256 CTAs

    // Pair map: X' = C + T X T, T = t2, C = t1 + t1@t2.
    // out ≈ S_8 + t1 (series tail ~3e-5 rel).  Doubling: U=P@S; S'=S+U@P; P'=P@P.
    //
    // L1: S1 = t1 + t1c@t2c -> sA  ||  P2 = t2c@t2c -> pA
    gemm_nn<<<g2, NTH, SMEM_TOTAL>>>(t1c, t2c, t1, 1.0f, nullptr, sA, 1,
                                     t2c, t2c, pA);
    // L2: U = t2c@S1
    gemm_nn<<<g1, NTH, SMEM_TOTAL>>>(t2c, sA, nullptr, 0.0f, nullptr, U, 1,
                                     nullptr, nullptr, nullptr);
    // L3: S2 = S1 + U@t2c -> sB
    gemm_nn<<<g1, NTH, SMEM_TOTAL>>>(U, t2c, sA, 1.0f, nullptr, sB, 1,
                                     nullptr, nullptr, nullptr);
    // L4: U2 = P2@S2 -> U  ||  P4 = P2@P2 -> pB
    gemm_nn<<<g2, NTH, SMEM_TOTAL>>>(pA, sB, nullptr, 0.0f, nullptr, U, 1,
                                     pA, pA, pB);
    // L5: S4 = S2 + U2@P2 -> sA
    gemm_nn<<<g1, NTH, SMEM_TOTAL>>>(U, pA, sB, 1.0f, nullptr, sA, 1,
                                     nullptr, nullptr, nullptr);
    // L6: U3 = P4@S4 -> U
    gemm_nn<<<g1, NTH, SMEM_TOTAL>>>(pB, sA, nullptr, 0.0f, nullptr, U, 1,
                                     nullptr, nullptr, nullptr);
    // L7: out = S4 + U3@P4 + t1  (fp32, no rounding)
    gemm_nn<<<g1, NTH, SMEM_TOTAL>>>(U, pB, sA, 1.0f, t1, out, 0,
                                     nullptr, nullptr, nullptr);
}

// round 10
// speedup vs baseline: 1.3272x; 1.0951x over previous
#include <cuda_runtime.h>
#include <cstdint>

#define N_DIM 1024
#define BM 128
#define BN 64
#define BK 64
#define NKT (N_DIM / BK)           // 16
#define NTH 256                    // 8 warps: 4 (m) x 2 (n), warp tile 32x32

#define ABYTES (BM * BK * 4)       // 32768
#define BROW   288                 // 64 floats (256B) + 32B pad
#define BBYTES (BK * BROW)         // 18432
#define STAGE  (ABYTES + BBYTES)   // 51200
#define SMEM_TOTAL (2 * STAGE)     // 102400

// scratch (allocation-free rules)
__device__ float g_t1c[N_DIM * N_DIM];   // tf32(t1)
__device__ float g_t2c[N_DIM * N_DIM];   // tf32(t2) = P_1
__device__ float g_sA [N_DIM * N_DIM];
__device__ float g_sB [N_DIM * N_DIM];
__device__ float g_pA [N_DIM * N_DIM];
__device__ float g_pB [N_DIM * N_DIM];
__device__ float g_U  [N_DIM * N_DIM];

__device__ __forceinline__ uint32_t smem_u32(const void* p) {
    uint32_t r;
    asm("{ .reg .u64 t; cvta.to.shared.u64 t, %1; cvt.u32.u64 %0, t; }" : "=r"(r) : "l"(p));
    return r;
}
__device__ __forceinline__ float to_tf32(float x) {
    uint32_t u;
    asm("cvt.rna.tf32.f32 %0, %1;" : "=r"(u) : "f"(x));
    return __uint_as_float(u);
}
__device__ __forceinline__ void cp16(uint32_t dst, const float* src) {
    asm volatile("cp.async.cg.shared.global [%0], [%1], 16;"
                 :: "r"(dst), "l"(src) : "memory");
}
__device__ __forceinline__ void ldm_x4(uint32_t* r, uint32_t addr) {
    asm volatile("ldmatrix.sync.aligned.m8n8.x4.shared.b16 {%0,%1,%2,%3}, [%4];"
                 : "=r"(r[0]), "=r"(r[1]), "=r"(r[2]), "=r"(r[3]) : "r"(addr));
}
__device__ __forceinline__ uint32_t lds32(uint32_t addr) {
    uint32_t v;
    asm volatile("ld.shared.b32 %0, [%1];" : "=r"(v) : "r"(addr));
    return v;
}
__device__ __forceinline__ void mma_tf32(float* d, const uint32_t* a,
                                         uint32_t b0, uint32_t b1) {
    asm volatile(
        "mma.sync.aligned.m16n8k8.row.col.f32.tf32.tf32.f32 "
        "{%0,%1,%2,%3}, {%4,%5,%6,%7}, {%8,%9}, {%0,%1,%2,%3};"
        : "+f"(d[0]), "+f"(d[1]), "+f"(d[2]), "+f"(d[3])
        : "r"(a[0]), "r"(a[1]), "r"(a[2]), "r"(a[3]), "r"(b0), "r"(b1));
}

// A tile [BM x BK] via cp.async, K-major swizzled smem (row = m, 256B rows, 16 chunks)
__device__ __forceinline__ void issueA(const float* __restrict__ A,
                                       int bm, int k0, uint32_t base, int tid) {
#pragma unroll
    for (int i = 0; i < 8; i++) {            // 2048 chunks / 256 threads
        int f = tid + i * NTH;
        int row = f >> 4, c = f & 15;
        uint32_t dst = base + row * 256 + ((c ^ (row & 7)) << 4);
        cp16(dst, A + (size_t)(bm + row) * N_DIM + k0 + c * 4);
    }
}

// B tile [BK x BN] via cp.async in NATURAL layout (row = k, 256B data + 32B pad)
__device__ __forceinline__ void issueB(const float* __restrict__ B,
                                       int bn, int k0, uint32_t base, int tid) {
#pragma unroll
    for (int i = 0; i < 4; i++) {            // 1024 chunks / 256 threads
        int f = tid + i * NTH;
        int k = f >> 4, c = f & 15;
        uint32_t dst = base + k * BROW + c * 16;
        cp16(dst, B + (size_t)(k0 + k) * N_DIM + bn + c * 4);
    }
}

// load fragments for one ks step (A via ldmatrix, B via LDS.32)
__device__ __forceinline__ void load_frags(uint32_t Ab, uint32_t Bb, int ks,
                                           int a_row, int a_chs, uint32_t b_off,
                                           uint32_t a[2][4],
                                           uint32_t* b0, uint32_t* b1) {
#pragma unroll
    for (int mf = 0; mf < 2; mf++) {
        int row = a_row + mf * 16;
        int ch = ks * 2 + a_chs;
        ldm_x4(a[mf], Ab + row * 256 + ((ch ^ (row & 7)) << 4));
    }
    const uint32_t bbase = Bb + ks * 8 * BROW + b_off;
#pragma unroll
    for (int nf = 0; nf < 4; nf++) {
        b0[nf] = lds32(bbase + nf * 32);
        b1[nf] = lds32(bbase + 4 * BROW + nf * 32);
    }
}

// z=0: C = bs*Bias + Bias2 + A@B (round if rnd). z=1: C1 = A1@B1 (rounded).
__global__ void __launch_bounds__(NTH)
gemm_nn(const float* __restrict__ A, const float* __restrict__ B,
        const float* __restrict__ Bias, float bs,
        const float* __restrict__ Bias2,
        float* __restrict__ C, int rnd,
        const float* __restrict__ A1, const float* __restrict__ B1,
        float* __restrict__ C1)
{
    if (blockIdx.z) {
        A = A1; B = B1; C = C1;
        Bias = nullptr; Bias2 = nullptr; rnd = 1;
    }
    extern __shared__ char smem[];
    const uint32_t sb = smem_u32(smem);
    const int tid = threadIdx.x, lid = tid & 31, wid = tid >> 5;
    const int wm = (wid & 3) * 32, wn = (wid >> 2) * 32;   // 4x2 warps, 32x32 tiles
    const int bm = blockIdx.y * BM, bn = blockIdx.x * BN;

    float d[2][4][4];
#pragma unroll
    for (int i = 0; i < 2; i++)
#pragma unroll
        for (int j = 0; j < 4; j++)
#pragma unroll
            for (int k = 0; k < 4; k++) d[i][j][k] = 0.0f;

    const int sub = lid >> 3;
    const int r8  = lid & 7;
    const int a_row = wm + (sub & 1) * 8 + r8;
    const int a_chs = (sub >> 1);
    // B fragment (m16n8k8 tf32): b0 at (k = lid%4, n = lid/4), b1 at k+4
    const uint32_t b_off = (uint32_t)((lid & 3) * BROW + (wn + (lid >> 2)) * 4);

    issueA(A, bm, 0, sb, tid);
    issueB(B, bn, 0, sb + ABYTES, tid);
    asm volatile("cp.async.commit_group;" ::: "memory");

    for (int kt = 0; kt < NKT; kt++) {
        const uint32_t buf = sb + (kt & 1) * STAGE;
        if (kt + 1 < NKT) {
            const uint32_t nbuf = sb + ((kt + 1) & 1) * STAGE;
            issueA(A, bm, (kt + 1) * BK, nbuf, tid);
            issueB(B, bn, (kt + 1) * BK, nbuf + ABYTES, tid);
            asm volatile("cp.async.commit_group;" ::: "memory");
            asm volatile("cp.async.wait_group 1;" ::: "memory");
        } else {
            asm volatile("cp.async.wait_group 0;" ::: "memory");
        }
        __syncthreads();

        const uint32_t Ab = buf;
        const uint32_t Bb = buf + ABYTES;

        // register-pipelined ks loop: load frags(ks+1) before MMAs(ks)
        uint32_t a[2][2][4], b0[2][4], b1[2][4];
        load_frags(Ab, Bb, 0, a_row, a_chs, b_off, a[0], b0[0], b1[0]);
#pragma unroll
        for (int ks = 0; ks < 8; ks++) {
            const int c = ks & 1, nx = c ^ 1;
            if (ks < 7)
                load_frags(Ab, Bb, ks + 1, a_row, a_chs, b_off, a[nx], b0[nx], b1[nx]);
#pragma unroll
            for (int mf = 0; mf < 2; mf++)
#pragma unroll
                for (int nf = 0; nf < 4; nf++)
                    mma_tf32(d[mf][nf], a[c][mf], b0[c][nf], b1[c][nf]);
        }
        __syncthreads();
    }

    const int g = lid >> 2, t = lid & 3;
#pragma unroll
    for (int mf = 0; mf < 2; mf++) {
#pragma unroll
        for (int nf = 0; nf < 4; nf++) {
            int row0 = bm + wm + mf * 16 + g;
            int col = bn + wn + nf * 8 + 2 * t;
            size_t off = (size_t)row0 * N_DIM + col;
            float2 o0 = make_float2(d[mf][nf][0], d[mf][nf][1]);
            float2 o1 = make_float2(d[mf][nf][2], d[mf][nf][3]);
            if (Bias) {
                const float* bp0 = Bias + off;
                float2 t0 = *reinterpret_cast<const float2*>(bp0);
                float2 t1v = *reinterpret_cast<const float2*>(bp0 + 8 * N_DIM);
                o0.x = fmaf(bs, t0.x, o0.x);
                o0.y = fmaf(bs, t0.y, o0.y);
                o1.x = fmaf(bs, t1v.x, o1.x);
                o1.y = fmaf(bs, t1v.y, o1.y);
            }
            if (Bias2) {
                const float* b2 = Bias2 + off;
                float2 u0 = *reinterpret_cast<const float2*>(b2);
                float2 u1 = *reinterpret_cast<const float2*>(b2 + 8 * N_DIM);
                o0.x += u0.x; o0.y += u0.y;
                o1.x += u1.x; o1.y += u1.y;
            }
            if (rnd) {
                o0.x = to_tf32(o0.x); o0.y = to_tf32(o0.y);
                o1.x = to_tf32(o1.x); o1.y = to_tf32(o1.y);
            }
            float* cp0 = C + off;
            *reinterpret_cast<float2*>(cp0) = o0;
            *reinterpret_cast<float2*>(cp0 + 8 * N_DIM) = o1;
        }
    }
}

// grid (1024, 2): y=0 rounds t1 -> o1, y=1 rounds t2 -> o2
__global__ void __launch_bounds__(256)
cvt2_k(const float* __restrict__ i1, const float* __restrict__ i2,
       float* __restrict__ o1, float* __restrict__ o2) {
    const float* in = blockIdx.y ? i2 : i1;
    float* out = blockIdx.y ? o2 : o1;
    int i = (blockIdx.x * 256 + threadIdx.x) * 4;
    float4 v = *reinterpret_cast<const float4*>(in + i);
    v.x = to_tf32(v.x); v.y = to_tf32(v.y);
    v.z = to_tf32(v.z); v.w = to_tf32(v.w);
    *reinterpret_cast<float4*>(out + i) = v;
}

extern "C" void kernel_launch(void* const* d_in, const int* in_sizes, int n_in,
                              void* d_out, int out_size)
{
    const float* t1 = (const float*)d_in[0];
    const float* t2 = (const float*)d_in[1];
    float* out = (float*)d_out;

    float *t1c, *t2c, *sA, *sB, *pA, *pB, *U;
    cudaGetSymbolAddress((void**)&t1c, g_t1c);
    cudaGetSymbolAddress((void**)&t2c, g_t2c);
    cudaGetSymbolAddress((void**)&sA, g_sA);
    cudaGetSymbolAddress((void**)&sB, g_sB);
    cudaGetSymbolAddress((void**)&pA, g_pA);
    cudaGetSymbolAddress((void**)&pB, g_pB);
    cudaGetSymbolAddress((void**)&U, g_U);

    cudaFuncSetAttribute(gemm_nn, cudaFuncAttributeMaxDynamicSharedMemorySize, SMEM_TOTAL);

    cvt2_k<<<dim3(N_DIM * N_DIM / 1024, 2), 256>>>(t1, t2, t1c, t2c);

    dim3 g1(N_DIM / BN, N_DIM / BM, 1);   // (16,8) = 128 CTAs
    dim3 g2(N_DIM / BN, N_DIM / BM, 2);   // merged pair: 256 CTAs

    // Pair map: X' = C + T X T, T = t2, C = t1 + t1@t2.
    // out ≈ S_8 + t1 (series tail ~3e-5 rel).  Doubling: U=P@S; S'=S+U@P; P'=P@P.
    //
    // L1: S1 = t1 + t1c@t2c -> sA  ||  P2 = t2c@t2c -> pA
    gemm_nn<<<g2, NTH, SMEM_TOTAL>>>(t1c, t2c, t1, 1.0f, nullptr, sA, 1,
                                     t2c, t2c, pA);
    // L2: U = t2c@S1
    gemm_nn<<<g1, NTH, SMEM_TOTAL>>>(t2c, sA, nullptr, 0.0f, nullptr, U, 1,
                                     nullptr, nullptr, nullptr);
    // L3: S2 = S1 + U@t2c -> sB
    gemm_nn<<<g1, NTH, SMEM_TOTAL>>>(U, t2c, sA, 1.0f, nullptr, sB, 1,
                                     nullptr, nullptr, nullptr);
    // L4: U2 = P2@S2 -> U  ||  P4 = P2@P2 -> pB
    gemm_nn<<<g2, NTH, SMEM_TOTAL>>>(pA, sB, nullptr, 0.0f, nullptr, U, 1,
                                     pA, pA, pB);
    // L5: S4 = S2 + U2@P2 -> sA
    gemm_nn<<<g1, NTH, SMEM_TOTAL>>>(U, pA, sB, 1.0f, nullptr, sA, 1,
                                     nullptr, nullptr, nullptr);
    // L6: U3 = P4@S4 -> U
    gemm_nn<<<g1, NTH, SMEM_TOTAL>>>(pB, sA, nullptr, 0.0f, nullptr, U, 1,
                                     nullptr, nullptr, nullptr);
    // L7: out = S4 + U3@P4 + t1  (fp32, no rounding)
    gemm_nn<<<g1, NTH, SMEM_TOTAL>>>(U, pB, sA, 1.0f, t1, out, 0,
                                     nullptr, nullptr, nullptr);
}